// round 16
// baseline (speedup 1.0000x reference)
#include <cuda_runtime.h>
#include <cstdint>

#define FULLMASK 0xffffffffu

constexpr int D        = 128;   // embedding dim (GEMM K)
constexpr int K        = 64;    // categorical dim (GEMM N)
constexpr int BM       = 64;    // batch rows per block
constexpr int NTHREADS = 256;
constexpr int NNEG     = 5;
constexpr int MAXBLOCKS = 4096;

constexpr int AST = 136;        // bf16 tile row stride (272 B) — conflict-free ldmatrix
constexpr int QS  = 68;         // sQ/sP row stride in floats (272 B) — conflict-free

// smem layout (bytes):
constexpr int OFF_AHI = 0;                       // A hi: [128][136] bf16 = 34816
constexpr int OFF_ALO = 34816;                   // A lo
constexpr int OFF_WHI = 69632;                   // W hi: [64][136] bf16 = 17408
constexpr int OFF_WLO = 69632 + 17408;           // W lo
constexpr int SMEM_BYTES = OFF_WLO + 17408;      // 104448 -> 2 blocks/SM
// epilogue overlay: sQ floats at byte 0 (64*68*4=17408), sP at 17408

__device__ float        g_partials[MAXBLOCKS];
__device__ unsigned int g_counter = 0;

// ---------------- warp helpers ----------------
__device__ __forceinline__ float wsum(float v) {
    #pragma unroll
    for (int o = 16; o > 0; o >>= 1) v += __shfl_xor_sync(FULLMASK, v, o);
    return v;
}
__device__ __forceinline__ float wmax(float v) {
    #pragma unroll
    for (int o = 16; o > 0; o >>= 1) v = fmaxf(v, __shfl_xor_sync(FULLMASK, v, o));
    return v;
}
__device__ __forceinline__ float dot4(float4 a, float4 b) {
    return fmaf(a.x, b.x, fmaf(a.y, b.y, fmaf(a.z, b.z, a.w * b.w)));
}
__device__ __forceinline__ float log_sigmoid(float x) {
    float e = __expf(-fabsf(x));
    return fminf(x, 0.0f) - __logf(1.0f + e);
}

// ---------------- hand-rolled bf16 (NO cuda_bf16.h) ----------------
// round-to-nearest-even truncation of fp32 to bf16 bits (inputs are finite,
// well-scaled N(0,1)-ish values; NaN/Inf not produced by this workload)
__device__ __forceinline__ uint32_t f2bf_bits(float x) {
    uint32_t u = __float_as_uint(x);
    return (u + 0x7FFFu + ((u >> 16) & 1u)) >> 16;    // 16-bit result
}
__device__ __forceinline__ float bfbits2f(uint32_t h) {
    return __uint_as_float(h << 16);
}
// 4 floats -> packed hi bf16x2 words + lo (residual) bf16x2 words
__device__ __forceinline__ void cvt4(float4 v, uint2& hi, uint2& lo) {
    uint32_t h0 = f2bf_bits(v.x), h1 = f2bf_bits(v.y);
    uint32_t h2 = f2bf_bits(v.z), h3 = f2bf_bits(v.w);
    float r0 = v.x - bfbits2f(h0);
    float r1 = v.y - bfbits2f(h1);
    float r2 = v.z - bfbits2f(h2);
    float r3 = v.w - bfbits2f(h3);
    uint32_t l0 = f2bf_bits(r0), l1 = f2bf_bits(r1);
    uint32_t l2 = f2bf_bits(r2), l3 = f2bf_bits(r3);
    hi = make_uint2(h0 | (h1 << 16), h2 | (h3 << 16));
    lo = make_uint2(l0 | (l1 << 16), l2 | (l3 << 16));
}

#define LDSM_X4(r0, r1, r2, r3, addr)                                          \
    asm volatile("ldmatrix.sync.aligned.m8n8.x4.shared.b16 {%0,%1,%2,%3}, [%4];" \
                 : "=r"(r0), "=r"(r1), "=r"(r2), "=r"(r3) : "r"(addr))

#define MMA16816(c, a0, a1, a2, a3, b0, b1)                                    \
    asm volatile("mma.sync.aligned.m16n8k16.row.col.f32.bf16.bf16.f32 "        \
                 "{%0,%1,%2,%3}, {%4,%5,%6,%7}, {%8,%9}, {%0,%1,%2,%3};"       \
                 : "+f"((c)[0]), "+f"((c)[1]), "+f"((c)[2]), "+f"((c)[3])      \
                 : "r"(a0), "r"(a1), "r"(a2), "r"(a3), "r"(b0), "r"(b1))

// =============================================================================
// Fused kernel: gather + bf16-split HMMA GEMM (q & prior fused, M=128) +
// softmax/argmax + loss + deterministic reduction.
// =============================================================================
__global__ __launch_bounds__(NTHREADS, 2)
void gcn_gumbel_mega(const int*   __restrict__ widx,
                     const int*   __restrict__ cidx,
                     const int*   __restrict__ negidx,
                     const float* __restrict__ gumbel,
                     const float* __restrict__ node_emb,
                     const float* __restrict__ ctx_emb,
                     const float* __restrict__ Wg,       // community_w [K][D]
                     float*       __restrict__ out0,
                     float*       __restrict__ outq,
                     float*       __restrict__ outp,
                     int Btot, float invB)
{
    extern __shared__ char sm[];
    const uint32_t sbase = (uint32_t)__cvta_generic_to_shared(sm);

    __shared__ float sred[8];
    __shared__ int   s_last;

    const int tid  = threadIdx.x;
    const int lane = tid & 31;
    const int warp = tid >> 5;
    const int b0   = blockIdx.x * BM;

    // ---- Phase 1a: gather w_e, c_e -> prod rows [0,64), w_e rows [64,128) ----
    {
        int r  = tid >> 2;             // 0..63
        int q4 = tid & 3;              // quarter of D
        int b  = min(b0 + r, Btot - 1);
        int wi = widx[b];
        int ci = cidx[b];
        const float4* wp = (const float4*)(node_emb + (size_t)wi * D + q4 * 32);
        const float4* cp = (const float4*)(node_emb + (size_t)ci * D + q4 * 32);
        #pragma unroll
        for (int j = 0; j < 8; j++) {
            float4 wv = __ldg(wp + j);
            float4 cv = __ldg(cp + j);
            float4 pv = make_float4(wv.x * cv.x, wv.y * cv.y, wv.z * cv.z, wv.w * cv.w);
            int d0 = q4 * 32 + j * 4;
            uint2 hi, lo;
            cvt4(pv, hi, lo);                       // prod -> row r
            *(uint2*)(sm + OFF_AHI + r * (AST * 2) + d0 * 2) = hi;
            *(uint2*)(sm + OFF_ALO + r * (AST * 2) + d0 * 2) = lo;
            cvt4(wv, hi, lo);                       // w_e -> row 64 + r
            *(uint2*)(sm + OFF_AHI + (64 + r) * (AST * 2) + d0 * 2) = hi;
            *(uint2*)(sm + OFF_ALO + (64 + r) * (AST * 2) + d0 * 2) = lo;
        }
    }
    // ---- Phase 1b: W -> bf16 hi/lo, n-major [64][AST] ----
    {
        int n  = tid >> 2;             // 0..63
        int q4 = tid & 3;
        const float4* wr = (const float4*)(Wg + (size_t)n * D + q4 * 32);
        #pragma unroll
        for (int j = 0; j < 8; j++) {
            float4 v = __ldg(wr + j);
            int d0 = q4 * 32 + j * 4;
            uint2 hi, lo;
            cvt4(v, hi, lo);
            *(uint2*)(sm + OFF_WHI + n * (AST * 2) + d0 * 2) = hi;
            *(uint2*)(sm + OFF_WLO + n * (AST * 2) + d0 * 2) = lo;
        }
    }
    __syncthreads();

    // ---- Phase 2: HMMA GEMM. warp w owns m rows [16w, 16w+16), all N=64 ----
    float c[8][4];
    #pragma unroll
    for (int i = 0; i < 8; i++)
        #pragma unroll
        for (int j = 0; j < 4; j++) c[i][j] = 0.0f;

    {
        const int mb  = warp * 16;
        const int g8  = lane & 7;      // row within 8-group
        const int grp = lane >> 3;     // ldmatrix address group 0..3

        #pragma unroll
        for (int term = 0; term < 3; term++) {
            // term 0: Ahi*Whi, term 1: Ahi*Wlo, term 2: Alo*Whi
            uint32_t Ab = sbase + ((term == 2) ? OFF_ALO : OFF_AHI);
            uint32_t Bb = sbase + ((term == 1) ? OFF_WLO : OFF_WHI);
            // A groups: 0:(rows+0,kh0) 1:(rows+8,kh0) 2:(rows+0,kh1) 3:(rows+8,kh1)
            uint32_t arow = Ab + (uint32_t)(mb + g8 + (grp & 1) * 8) * (AST * 2)
                               + (uint32_t)(grp >> 1) * 16;
            // B groups: 0:(n+0,kh0) 1:(n+0,kh1) 2:(n+8,kh0) 3:(n+8,kh1)
            uint32_t brow = Bb + (uint32_t)(g8 + (grp >> 1) * 8) * (AST * 2)
                               + (uint32_t)(grp & 1) * 16;
            #pragma unroll
            for (int kt = 0; kt < 8; kt++) {
                uint32_t a0, a1, a2, a3;
                LDSM_X4(a0, a1, a2, a3, arow + kt * 32);
                #pragma unroll
                for (int nt2 = 0; nt2 < 4; nt2++) {
                    uint32_t b0, b1, b2, b3;
                    LDSM_X4(b0, b1, b2, b3, brow + (uint32_t)nt2 * 16 * (AST * 2) + kt * 32);
                    MMA16816(c[nt2 * 2],     a0, a1, a2, a3, b0, b1);
                    MMA16816(c[nt2 * 2 + 1], a0, a1, a2, a3, b2, b3);
                }
            }
        }
    }
    __syncthreads();   // all GEMM smem reads done before overlay

    // ---- Phase 3: dump logits. warps 0-3 -> sQ (q), warps 4-7 -> sP (prior) ----
    float* sQ = (float*)sm;                 // [64][QS]
    float* sP = (float*)(sm + 17408);       // [64][QS]
    {
        int g = lane >> 2, t = lane & 3;
        float* dst = (warp < 4) ? sQ : sP;
        int rl = (warp & 3) * 16 + g;
        #pragma unroll
        for (int nt = 0; nt < 8; nt++) {
            *(float2*)&dst[rl * QS + nt * 8 + 2 * t]       = make_float2(c[nt][0], c[nt][1]);
            *(float2*)&dst[(rl + 8) * QS + nt * 8 + 2 * t] = make_float2(c[nt][2], c[nt][3]);
        }
    }
    __syncthreads();

    // ---- Phase 4+5: per-warp rows (8 rows per warp) ----
    float lacc = 0.0f;
    for (int j = 0; j < 8; j++) {
        int r = warp * 8 + j;
        int b = b0 + r;
        if (b >= Btot) break;

        // issue all independent loads first
        int ci = cidx[b];
        int n0 = negidx[(size_t)b * NNEG + 0];
        int n1 = negidx[(size_t)b * NNEG + 1];
        int n2 = negidx[(size_t)b * NNEG + 2];
        int n3 = negidx[(size_t)b * NNEG + 3];
        int n4 = negidx[(size_t)b * NNEG + 4];
        float4 cv = *(const float4*)(ctx_emb + (size_t)ci * D + (lane << 2));
        float4 v0 = *(const float4*)(ctx_emb + (size_t)n0 * D + (lane << 2));
        float4 v1 = *(const float4*)(ctx_emb + (size_t)n1 * D + (lane << 2));
        float4 v2 = *(const float4*)(ctx_emb + (size_t)n2 * D + (lane << 2));
        float4 v3 = *(const float4*)(ctx_emb + (size_t)n3 * D + (lane << 2));
        float4 v4 = *(const float4*)(ctx_emb + (size_t)n4 * D + (lane << 2));
        float g1 = __ldcs(gumbel + (size_t)b * K + lane);
        float g2 = __ldcs(gumbel + (size_t)b * K + 32 + lane);
        float q1 = sQ[r * QS + lane];
        float q2 = sQ[r * QS + 32 + lane];
        float p1 = sP[r * QS + lane];
        float p2 = sP[r * QS + 32 + lane];

        // argmax(q + gumbel) first so the W[k*] gather flies early
        float av = q1 + g1;
        int   ai = lane;
        {
            float a2v = q2 + g2;
            if (a2v > av) { av = a2v; ai = lane + 32; }
        }
        float    mv  = wmax(av);
        unsigned msk = __ballot_sync(FULLMASK, av == mv);
        int      kst = __shfl_sync(FULLMASK, ai, __ffs(msk) - 1);
        float4 wv = *(const float4*)(Wg + (size_t)kst * D + (lane << 2));

        // softmax(q)
        float mq  = wmax(fmaxf(q1, q2));
        float e1  = __expf(q1 - mq);
        float e2  = __expf(q2 - mq);
        float inv = __fdividef(1.0f, wsum(e1 + e2));
        __stcs(outq + (size_t)b * K + lane,      e1 * inv);
        __stcs(outq + (size_t)b * K + 32 + lane, e2 * inv);

        // softmax(prior)
        float mp = wmax(fmaxf(p1, p2));
        float f1 = __expf(p1 - mp);
        float f2 = __expf(p2 - mp);
        float ip = __fdividef(1.0f, wsum(f1 + f2));
        __stcs(outp + (size_t)b * K + lane,      f1 * ip);
        __stcs(outp + (size_t)b * K + 32 + lane, f2 * ip);

        // loss dots with W[k*]
        float s0 = dot4(wv, cv);
        float s1 = dot4(wv, v0);
        float s2 = dot4(wv, v1);
        float s3 = dot4(wv, v2);
        float s4 = dot4(wv, v3);
        float s5 = dot4(wv, v4);
        s0 = wsum(s0); s1 = wsum(s1); s2 = wsum(s2);
        s3 = wsum(s3); s4 = wsum(s4); s5 = wsum(s5);

        float term = log_sigmoid(s0);
        float nsum = log_sigmoid(-s1) + log_sigmoid(-s2) + log_sigmoid(-s3)
                   + log_sigmoid(-s4) + log_sigmoid(-s5);
        term = fmaf(nsum, 1.0f / (float)NNEG, term);
        if (lane == 0) lacc += term;
    }

    // ---- block partial + last-block deterministic reduce ----
    if (lane == 0) sred[warp] = lacc;
    __syncthreads();
    if (tid == 0) {
        float s = 0.0f;
        #pragma unroll
        for (int i = 0; i < 8; i++) s += sred[i];
        g_partials[blockIdx.x] = s;
        __threadfence();
        unsigned t = atomicAdd(&g_counter, 1u);
        s_last = (t == gridDim.x - 1) ? 1 : 0;
    }
    __syncthreads();

    if (s_last) {
        float* scratch = (float*)sm;
        float s = 0.0f;
        for (int i = tid; i < (int)gridDim.x; i += NTHREADS)
            s += __ldcg(&g_partials[i]);
        scratch[tid] = s;
        __syncthreads();
        #pragma unroll
        for (int o = NTHREADS / 2; o > 0; o >>= 1) {
            if (tid < o) scratch[tid] += scratch[tid + o];
            __syncthreads();
        }
        if (tid == 0) {
            out0[0] = -scratch[0] * invB;
            g_counter = 0;
        }
    }
}

// =============================================================================
extern "C" void kernel_launch(void* const* d_in, const int* in_sizes, int n_in,
                              void* d_out, int out_size)
{
    const int*   w        = (const int*)  d_in[0];
    const int*   c        = (const int*)  d_in[1];
    const int*   neg      = (const int*)  d_in[2];
    // d_in[3] = temp (==1): only rescales the argmax input -> provably irrelevant
    const float* gumbel   = (const float*)d_in[4];
    const float* node_emb = (const float*)d_in[5];
    const float* ctx_emb  = (const float*)d_in[6];
    const float* Wg       = (const float*)d_in[7];

    const int B = in_sizes[0];

    float* out       = (float*)d_out;
    float* out_q     = out + 1;
    float* out_prior = out + 1 + (size_t)B * K;

    int nb = (B + BM - 1) / BM;     // 2048
    if (nb > MAXBLOCKS) nb = MAXBLOCKS;

    cudaFuncSetAttribute(gcn_gumbel_mega,
                         cudaFuncAttributeMaxDynamicSharedMemorySize, SMEM_BYTES);

    gcn_gumbel_mega<<<nb, NTHREADS, SMEM_BYTES>>>(
        w, c, neg, gumbel, node_emb, ctx_emb, Wg,
        out, out_q, out_prior, B, 1.0f / (float)B);
}